// round 4
// baseline (speedup 1.0000x reference)
#include <cuda_runtime.h>
#include <cuda_bf16.h>
#include <math.h>

// Problem constants (fixed by setup_inputs)
#define HDIM 512
#define NDIM 32
#define LLEN 4096
#define LF   2049   // LLEN/2 + 1

// Scratch for the frequency-domain kernel k_f[h][l] (complex64)
__device__ float2 g_kf[HDIM * LF];

// ---------------------------------------------------------------------------
// Kernel 1: Cauchy sums + rank-1 Woodbury correction + bilinear scaling.
//
// For each (h, l):  z_l = 2i*tan(pi*l/L)  (purely imaginary, y = 2 tan)
//   r_ab = dt_h * sum_n [ v_ab/(z - wdt) + conj(v_ab)/(z - conj(wdt)) ]
//   k_f  = (r00 - r01*r10/(1+r11)) * (1 + i*y/2)
// l == L/2 is the analytic limit: k_f = dt * Re(sum_n B*C), purely real.
// ---------------------------------------------------------------------------
__global__ void cauchy_kernel(const float* __restrict__ w_re, const float* __restrict__ w_im,
                              const float* __restrict__ p_re, const float* __restrict__ p_im,
                              const float* __restrict__ B_re, const float* __restrict__ B_im,
                              const float* __restrict__ C_re, const float* __restrict__ C_im,
                              const float* __restrict__ log_dt) {
    __shared__ float s_wr[NDIM],  s_wi[NDIM];
    __shared__ float s_v00r[NDIM], s_v00i[NDIM];
    __shared__ float s_v01r[NDIM], s_v01i[NDIM];
    __shared__ float s_v10r[NDIM], s_v10i[NDIM];
    __shared__ float s_v11r[NDIM];                 // v11 = |P|^2, purely real

    const int h   = blockIdx.y;
    const int tid = threadIdx.x;
    const float dt = expf(log_dt[h]);

    if (tid < NDIM) {
        const int idx = h * NDIM + tid;
        const float wr = w_re[idx] * dt, wi = w_im[idx] * dt;  // wdt
        s_wr[tid] = wr; s_wi[tid] = wi;
        const float br = B_re[idx], bi = B_im[idx];
        const float cr = C_re[idx], ci = C_im[idx];
        const float pr = p_re[idx], pi = p_im[idx];
        s_v00r[tid] = br * cr - bi * ci;   s_v00i[tid] = br * ci + bi * cr;   // B*C
        s_v01r[tid] = br * pr + bi * pi;   s_v01i[tid] = bi * pr - br * pi;   // B*conj(P)
        s_v10r[tid] = pr * cr - pi * ci;   s_v10i[tid] = pr * ci + pi * cr;   // P*C
        s_v11r[tid] = pr * pr + pi * pi;                                       // |P|^2
    }
    __syncthreads();

    const int l = blockIdx.x * blockDim.x + tid;
    if (l >= LF) return;

    if (l == LLEN / 2) {
        // Analytic Nyquist limit: k_f = dt * Re(sum_n B*C)
        float acc = 0.f;
        #pragma unroll
        for (int n = 0; n < NDIM; n++) acc += s_v00r[n];
        g_kf[h * LF + l] = make_float2(dt * acc, 0.f);
        return;
    }

    const float y = 2.0f * tanf((float)l * (float)(M_PI / (double)LLEN));

    float r00r = 0.f, r00i = 0.f, r01r = 0.f, r01i = 0.f;
    float r10r = 0.f, r10i = 0.f, r11r = 0.f, r11i = 0.f;

    #pragma unroll 8
    for (int n = 0; n < NDIM; n++) {
        const float wr = s_wr[n], wi = s_wi[n];
        const float ar  = -wr;
        const float ai1 = y - wi;           // z - wdt       = ar + i*ai1
        const float ai2 = y + wi;           // z - conj(wdt) = ar + i*ai2
        const float ar2 = ar * ar;
        const float inv1 = __frcp_rn(fmaf(ai1, ai1, ar2));
        const float inv2 = __frcp_rn(fmaf(ai2, ai2, ar2));
        const float d1r = ar * inv1, d1i = -ai1 * inv1;   // 1/(z - wdt)
        const float er  = ar * inv2, ei  = -ai2 * inv2;   // 1/(z - conj(wdt))
        // accumulate v*d1 + conj(v)*e:
        //   re += vr*(d1r+er) - vi*(d1i-ei)  = vr*sr - vi*ti
        //   im += vr*(d1i+ei) + vi*(d1r-er)  = vr*si + vi*tr
        const float sr = d1r + er, si = d1i + ei;
        const float tr = d1r - er, ti = d1i - ei;
        float vr, vi;
        vr = s_v00r[n]; vi = s_v00i[n];
        r00r += vr * sr - vi * ti;  r00i += vr * si + vi * tr;
        vr = s_v01r[n]; vi = s_v01i[n];
        r01r += vr * sr - vi * ti;  r01i += vr * si + vi * tr;
        vr = s_v10r[n]; vi = s_v10i[n];
        r10r += vr * sr - vi * ti;  r10i += vr * si + vi * tr;
        vr = s_v11r[n];
        r11r += vr * sr;            r11i += vr * si;
    }

    r00r *= dt; r00i *= dt; r01r *= dt; r01i *= dt;
    r10r *= dt; r10i *= dt; r11r *= dt; r11i *= dt;

    // Woodbury: k = r00 - r01*r10/(1+r11)
    const float dr = 1.f + r11r, di = r11i;
    const float dinv = __frcp_rn(dr * dr + di * di);
    const float qr = r01r * r10r - r01i * r10i;
    const float qi = r01r * r10i + r01i * r10r;
    const float cr2 = (qr * dr + qi * di) * dinv;
    const float ci2 = (qi * dr - qr * di) * dinv;
    const float kr = r00r - cr2, ki = r00i - ci2;

    // scale by 2/(1+omega) = 1 + i*(y/2)
    const float hy = 0.5f * y;
    g_kf[h * LF + l] = make_float2(kr - hy * ki, ki + hy * kr);
}

// ---------------------------------------------------------------------------
// Kernel 2: per-head 4096-point inverse FFT of the hermitian spectrum,
// real part / L is the output. In-place radix-2 DIT in shared memory with a
// half-size twiddle table (W^{j+1024} = i * W^j fold).
// ---------------------------------------------------------------------------
__global__ void ifft_kernel(float* __restrict__ out) {
    __shared__ float2 X[LLEN];          // 32 KB
    __shared__ float2 TW[LLEN / 4];     // 8 KB : W^j = e^{+2*pi*i*j/L}, j < 1024

    const int h   = blockIdx.x;
    const int tid = threadIdx.x;
    const int T   = blockDim.x;

    // Build quarter-circle twiddle table (inverse sign: +2pi)
    for (int j = tid; j < LLEN / 4; j += T) {
        float s, c;
        sincosf((float)j * (float)(2.0 * M_PI / (double)LLEN), &s, &c);
        TW[j] = make_float2(c, s);
    }

    // Load hermitian-extended spectrum in bit-reversed order
    const float2* kf = &g_kf[h * LF];
    for (int idx = tid; idx < LLEN; idx += T) {
        float2 v;
        if (idx <= LLEN / 2) {
            v = kf[idx];
        } else {
            const float2 t = kf[LLEN - idx];
            v = make_float2(t.x, -t.y);
        }
        const int rev = __brev((unsigned)idx) >> 20;   // 12-bit reverse
        X[rev] = v;
    }
    __syncthreads();

    // 12 DIT stages
    for (int s = 1; s <= 12; s++) {
        const int half  = 1 << (s - 1);
        const int shift = 12 - s;
        for (int j = tid; j < LLEN / 2; j += T) {
            const int k  = j & (half - 1);
            const int i0 = ((j >> (s - 1)) << s) | k;
            const int i1 = i0 + half;
            int twi = k << shift;                 // in [0, 2048)
            float2 w;
            if (twi < LLEN / 4) {
                w = TW[twi];
            } else {                              // W^{j+1024} = i*W^j
                const float2 t = TW[twi - LLEN / 4];
                w = make_float2(-t.y, t.x);
            }
            const float2 b = X[i1], a = X[i0];
            const float bwr = b.x * w.x - b.y * w.y;
            const float bwi = b.x * w.y + b.y * w.x;
            X[i0] = make_float2(a.x + bwr, a.y + bwi);
            X[i1] = make_float2(a.x - bwr, a.y - bwi);
        }
        __syncthreads();
    }

    const float scale = 1.0f / (float)LLEN;
    for (int t = tid; t < LLEN; t += T)
        out[h * LLEN + t] = X[t].x * scale;
}

// ---------------------------------------------------------------------------
// Inputs (metadata order): w_re, w_im, p_re, p_im, B_re, B_im, C_re, C_im,
// log_dt, L.  Shapes fixed; L hardcoded to 4096.
// Output: k[-1] -> (1, 512, 4096) float32, laid out [h][t].
// ---------------------------------------------------------------------------
extern "C" void kernel_launch(void* const* d_in, const int* in_sizes, int n_in,
                              void* d_out, int out_size) {
    const float* w_re   = (const float*)d_in[0];
    const float* w_im   = (const float*)d_in[1];
    const float* p_re   = (const float*)d_in[2];
    const float* p_im   = (const float*)d_in[3];
    const float* B_re   = (const float*)d_in[4];
    const float* B_im   = (const float*)d_in[5];
    const float* C_re   = (const float*)d_in[6];
    const float* C_im   = (const float*)d_in[7];
    const float* log_dt = (const float*)d_in[8];
    float* out = (float*)d_out;

    dim3 g1((LF + 255) / 256, HDIM);
    cauchy_kernel<<<g1, 256>>>(w_re, w_im, p_re, p_im, B_re, B_im, C_re, C_im, log_dt);
    ifft_kernel<<<HDIM, 256>>>(out);
}

// round 5
// speedup vs baseline: 1.2115x; 1.2115x over previous
#include <cuda_runtime.h>
#include <cuda_bf16.h>
#include <math.h>

// Problem constants (fixed by setup_inputs)
#define HDIM 512
#define NDIM 32
#define LLEN 4096
#define LF   2049   // LLEN/2 + 1

// Scratch for the frequency-domain kernel k_f[h][l] (complex64)
__device__ float2 g_kf[HDIM * LF];

// ---------------- packed f32x2 helpers (Blackwell FFMA2 path) --------------
typedef unsigned long long u64;
__device__ __forceinline__ u64 pk(float lo, float hi) {
    u64 r; asm("mov.b64 %0,{%1,%2};" : "=l"(r) : "f"(lo), "f"(hi)); return r;
}
__device__ __forceinline__ void upk(float& lo, float& hi, u64 v) {
    asm("mov.b64 {%0,%1},%2;" : "=f"(lo), "=f"(hi) : "l"(v));
}
__device__ __forceinline__ u64 f2add(u64 a, u64 b) {
    u64 d; asm("add.rn.f32x2 %0,%1,%2;" : "=l"(d) : "l"(a), "l"(b)); return d;
}
__device__ __forceinline__ u64 f2mul(u64 a, u64 b) {
    u64 d; asm("mul.rn.f32x2 %0,%1,%2;" : "=l"(d) : "l"(a), "l"(b)); return d;
}
__device__ __forceinline__ u64 f2fma(u64 a, u64 b, u64 c) {
    u64 d; asm("fma.rn.f32x2 %0,%1,%2,%3;" : "=l"(d) : "l"(a), "l"(b), "l"(c)); return d;
}

// ---------------------------------------------------------------------------
// Kernel 1: Cauchy sums + rank-1 Woodbury correction + bilinear scaling.
// Packed f32x2 inner loop: lanes hold (re, im) of each accumulator.
// v-values pre-scaled by dt at setup (so no trailing *dt).
// ---------------------------------------------------------------------------
__global__ void cauchy_kernel(const float* __restrict__ w_re, const float* __restrict__ w_im,
                              const float* __restrict__ p_re, const float* __restrict__ p_im,
                              const float* __restrict__ B_re, const float* __restrict__ B_im,
                              const float* __restrict__ C_re, const float* __restrict__ C_im,
                              const float* __restrict__ log_dt) {
    __shared__ u64 s_arwi[NDIM];   // (ar, wi)     ar = -wr*dt, wi = wi*dt
    __shared__ u64 s_armwi[NDIM];  // (ar, -wi)
    __shared__ u64 s_wipm[NDIM];   // (-wi, wi)
    __shared__ u64 s_ar2[NDIM];    // (ar^2, ar^2)
    __shared__ u64 s_v00r[NDIM], s_v00i[NDIM];   // dt * B*C        (dup lanes)
    __shared__ u64 s_v01r[NDIM], s_v01i[NDIM];   // dt * B*conj(P)
    __shared__ u64 s_v10r[NDIM], s_v10i[NDIM];   // dt * P*C
    __shared__ u64 s_v11r[NDIM];                 // dt * |P|^2 (real)

    const int h   = blockIdx.y;
    const int tid = threadIdx.x;
    const float dt = expf(log_dt[h]);

    if (tid < NDIM) {
        const int idx = h * NDIM + tid;
        const float wr = w_re[idx] * dt, wi = w_im[idx] * dt;
        const float ar = -wr;
        s_arwi[tid]  = pk(ar, wi);
        s_armwi[tid] = pk(ar, -wi);
        s_wipm[tid]  = pk(-wi, wi);
        s_ar2[tid]   = pk(ar * ar, ar * ar);
        const float br = B_re[idx], bi = B_im[idx];
        const float cr = C_re[idx], ci = C_im[idx];
        const float pr = p_re[idx], pi = p_im[idx];
        const float v00r = dt * (br * cr - bi * ci), v00i = dt * (br * ci + bi * cr);
        const float v01r = dt * (br * pr + bi * pi), v01i = dt * (bi * pr - br * pi);
        const float v10r = dt * (pr * cr - pi * ci), v10i = dt * (pr * ci + pi * cr);
        const float v11r = dt * (pr * pr + pi * pi);
        s_v00r[tid] = pk(v00r, v00r); s_v00i[tid] = pk(v00i, v00i);
        s_v01r[tid] = pk(v01r, v01r); s_v01i[tid] = pk(v01i, v01i);
        s_v10r[tid] = pk(v10r, v10r); s_v10i[tid] = pk(v10i, v10i);
        s_v11r[tid] = pk(v11r, v11r);
    }
    __syncthreads();

    const int l = blockIdx.x * blockDim.x + tid;
    if (l >= LF) return;

    if (l == LLEN / 2) {
        // Analytic Nyquist limit: k_f = dt * Re(sum_n B*C) (dt already folded in)
        float acc = 0.f;
        #pragma unroll
        for (int n = 0; n < NDIM; n++) { float a, b; upk(a, b, s_v00r[n]); acc += a; }
        g_kf[h * LF + l] = make_float2(acc, 0.f);
        return;
    }

    const float y = 2.0f * tanf((float)l * (float)(M_PI / (double)LLEN));
    const u64 y0m  = pk(0.f, -y);     // for n1/n2:  (ar, +/-wi) + (0, -y)
    const u64 ypp  = pk(y, y);        // for A:      (-wi, wi) + (y, y) = (ai1, ai2)
    const u64 NEG1 = pk(-1.f, -1.f);

    u64 r00 = 0ull, r01 = 0ull, r10 = 0ull, r11 = 0ull;

    #pragma unroll
    for (int n = 0; n < NDIM; n++) {
        const u64 n1 = f2add(s_arwi[n],  y0m);   // (ar, -ai1)  [ai1 = y - wi]
        const u64 n2 = f2add(s_armwi[n], y0m);   // (ar, -ai2)  [ai2 = y + wi]
        const u64 A  = f2add(s_wipm[n],  ypp);   // (ai1, ai2)
        const u64 den = f2fma(A, A, s_ar2[n]);   // (|z-wdt|^2, |z-conj|^2)
        float den1, den2; upk(den1, den2, den);
        const float inv1 = __frcp_rn(den1), inv2 = __frcp_rn(den2);
        const u64 d1 = f2mul(n1, pk(inv1, inv1));    // 1/(z - wdt)
        const u64 e  = f2mul(n2, pk(inv2, inv2));    // 1/(z - conj(wdt))
        const u64 s  = f2add(d1, e);                  // (sr, si)
        const u64 t  = f2fma(e, NEG1, d1);            // (tr, ti) = d1 - e
        float tr, ti; upk(tr, ti, t);
        const u64 u  = pk(-ti, tr);                   // i * t
        // row accum: (re,im) += vr*(sr,si) + vi*(-ti,tr)
        r00 = f2fma(s_v00r[n], s, r00);  r00 = f2fma(s_v00i[n], u, r00);
        r01 = f2fma(s_v01r[n], s, r01);  r01 = f2fma(s_v01i[n], u, r01);
        r10 = f2fma(s_v10r[n], s, r10);  r10 = f2fma(s_v10i[n], u, r10);
        r11 = f2fma(s_v11r[n], s, r11);
    }

    float r00r, r00i, r01r, r01i, r10r, r10i, r11r, r11i;
    upk(r00r, r00i, r00); upk(r01r, r01i, r01);
    upk(r10r, r10i, r10); upk(r11r, r11i, r11);

    // Woodbury: k = r00 - r01*r10/(1+r11)
    const float dr = 1.f + r11r, di = r11i;
    const float dinv = __frcp_rn(dr * dr + di * di);
    const float qr = r01r * r10r - r01i * r10i;
    const float qi = r01r * r10i + r01i * r10r;
    const float cr2 = (qr * dr + qi * di) * dinv;
    const float ci2 = (qi * dr - qr * di) * dinv;
    const float kr = r00r - cr2, ki = r00i - ci2;

    // scale by 2/(1+omega) = 1 + i*(y/2)
    const float hy = 0.5f * y;
    g_kf[h * LF + l] = make_float2(kr - hy * ki, ki + hy * kr);
}

// ---------------------------------------------------------------------------
// Kernel 2: per-head 4096-point inverse FFT, radix-4 DIT (6 stages),
// hermitian-extended input, real part / L out. Quarter twiddle table +
// i^q rotation fold.
// ---------------------------------------------------------------------------
__global__ void ifft_kernel(float* __restrict__ out) {
    __shared__ float2 X[LLEN];       // 32 KB
    __shared__ float2 TW[1024];      // 8 KB : W^j = e^{+2*pi*i*j/4096}, j < 1024

    const int h   = blockIdx.x;
    const int tid = threadIdx.x;

    for (int j = tid; j < 1024; j += 256) {
        float s, c;
        sincosf((float)j * (float)(2.0 * M_PI / (double)LLEN), &s, &c);
        TW[j] = make_float2(c, s);
    }

    // Load hermitian-extended spectrum in base-4 digit-reversed order
    const float2* kf = &g_kf[h * LF];
    for (int idx = tid; idx < LLEN; idx += 256) {
        float2 v;
        if (idx <= LLEN / 2) {
            v = kf[idx];
        } else {
            const float2 t = kf[LLEN - idx];
            v = make_float2(t.x, -t.y);
        }
        int r = __brev((unsigned)idx) >> 20;            // 12-bit bit-reverse
        r = ((r & 0x555) << 1) | ((r >> 1) & 0x555);    // -> base-4 digit reverse
        X[r] = v;
    }
    __syncthreads();

    // 6 radix-4 DIT stages (inverse: W = e^{+2pi i/N}, combine factors i^{qj})
    #pragma unroll
    for (int s = 0; s < 6; s++) {
        const int m    = 1 << (2 * s);        // sub-DFT size
        const int step = 1024 >> (2 * s);     // twiddle stride N/(4m)
        for (int j = tid; j < 1024; j += 256) {
            const int k    = j & (m - 1);
            const int base = ((j >> (2 * s)) << (2 * s + 2)) + k;
            const float2 t0 = X[base];
            const float2 x1 = X[base + m], x2 = X[base + 2 * m], x3 = X[base + 3 * m];

            const int e1 = k * step;                       // < 1024
            const float2 w1 = TW[e1];
            float2 w2; { const int e = 2 * e1; const float2 q = TW[e & 1023];
                         w2 = (e & 1024) ? make_float2(-q.y, q.x) : q; }
            float2 w3; { const int e = 3 * e1; const float2 q = TW[e & 1023];
                         const int qq = e >> 10;           // 0,1,2
                         w3 = (qq == 0) ? q : (qq == 1) ? make_float2(-q.y, q.x)
                                                        : make_float2(-q.x, -q.y); }

            const float2 t1 = make_float2(x1.x * w1.x - x1.y * w1.y, x1.x * w1.y + x1.y * w1.x);
            const float2 t2 = make_float2(x2.x * w2.x - x2.y * w2.y, x2.x * w2.y + x2.y * w2.x);
            const float2 t3 = make_float2(x3.x * w3.x - x3.y * w3.y, x3.x * w3.y + x3.y * w3.x);

            const float ax = t0.x + t2.x, ay = t0.y + t2.y;   // t0 + t2
            const float bx = t0.x - t2.x, by = t0.y - t2.y;   // t0 - t2
            const float cx = t1.x + t3.x, cy = t1.y + t3.y;   // t1 + t3
            const float dx = -(t1.y - t3.y), dy = t1.x - t3.x; // i*(t1 - t3)

            X[base]         = make_float2(ax + cx, ay + cy);  // y0
            X[base + m]     = make_float2(bx + dx, by + dy);  // y1
            X[base + 2 * m] = make_float2(ax - cx, ay - cy);  // y2
            X[base + 3 * m] = make_float2(bx - dx, by - dy);  // y3
        }
        __syncthreads();
    }

    const float scale = 1.0f / (float)LLEN;
    for (int t = tid; t < LLEN; t += 256)
        out[h * LLEN + t] = X[t].x * scale;
}

// ---------------------------------------------------------------------------
// Inputs (metadata order): w_re, w_im, p_re, p_im, B_re, B_im, C_re, C_im,
// log_dt, L.  Shapes fixed; L hardcoded to 4096.
// Output: k[-1] -> (1, 512, 4096) float32, laid out [h][t].
// ---------------------------------------------------------------------------
extern "C" void kernel_launch(void* const* d_in, const int* in_sizes, int n_in,
                              void* d_out, int out_size) {
    const float* w_re   = (const float*)d_in[0];
    const float* w_im   = (const float*)d_in[1];
    const float* p_re   = (const float*)d_in[2];
    const float* p_im   = (const float*)d_in[3];
    const float* B_re   = (const float*)d_in[4];
    const float* B_im   = (const float*)d_in[5];
    const float* C_re   = (const float*)d_in[6];
    const float* C_im   = (const float*)d_in[7];
    const float* log_dt = (const float*)d_in[8];
    float* out = (float*)d_out;

    dim3 g1((LF + 255) / 256, HDIM);
    cauchy_kernel<<<g1, 256>>>(w_re, w_im, p_re, p_im, B_re, B_im, C_re, C_im, log_dt);
    ifft_kernel<<<HDIM, 256>>>(out);
}

// round 6
// speedup vs baseline: 1.2315x; 1.0165x over previous
#include <cuda_runtime.h>
#include <cuda_bf16.h>
#include <math.h>

#define HDIM 512
#define NDIM 32
#define LLEN 4096
#define LF   2049   // LLEN/2 + 1

__device__ float2 g_kf[HDIM * LF];

// ---------------- packed f32x2 helpers (Blackwell FFMA2 path) --------------
typedef unsigned long long u64;
__device__ __forceinline__ u64 pk(float lo, float hi) {
    u64 r; asm("mov.b64 %0,{%1,%2};" : "=l"(r) : "f"(lo), "f"(hi)); return r;
}
__device__ __forceinline__ void upk(float& lo, float& hi, u64 v) {
    asm("mov.b64 {%0,%1},%2;" : "=f"(lo), "=f"(hi) : "l"(v));
}
__device__ __forceinline__ u64 f2add(u64 a, u64 b) {
    u64 d; asm("add.rn.f32x2 %0,%1,%2;" : "=l"(d) : "l"(a), "l"(b)); return d;
}
__device__ __forceinline__ u64 f2mul(u64 a, u64 b) {
    u64 d; asm("mul.rn.f32x2 %0,%1,%2;" : "=l"(d) : "l"(a), "l"(b)); return d;
}
__device__ __forceinline__ u64 f2fma(u64 a, u64 b, u64 c) {
    u64 d; asm("fma.rn.f32x2 %0,%1,%2,%3;" : "=l"(d) : "l"(a), "l"(b), "l"(c)); return d;
}

// ---------------------------------------------------------------------------
// Kernel 1: Cauchy sums + Woodbury + bilinear scale. Packed f32x2 lanes are
// (re, im). Each thread computes TWO l-values (l and l+256) so the two
// independent chains hide RCP/LDS latency and shared loads amortize.
// Grid: (4, HDIM) x 256 threads -> l = bx*512 + tid + {0,256} covers 0..2047.
// Nyquist l=2048 done by (bx=0, tid=0).
// ---------------------------------------------------------------------------
__global__ void cauchy_kernel(const float* __restrict__ w_re, const float* __restrict__ w_im,
                              const float* __restrict__ p_re, const float* __restrict__ p_im,
                              const float* __restrict__ B_re, const float* __restrict__ B_im,
                              const float* __restrict__ C_re, const float* __restrict__ C_im,
                              const float* __restrict__ log_dt) {
    __shared__ u64 s_arwi[NDIM];   // (ar,  wi)   ar = -wr*dt, wi = wi*dt
    __shared__ u64 s_armwi[NDIM];  // (ar, -wi)
    __shared__ u64 s_wipm[NDIM];   // (-wi, wi)
    __shared__ u64 s_ar2[NDIM];    // (ar^2, ar^2)
    __shared__ u64 s_v00r[NDIM], s_v00n[NDIM];   // vr dup ; (-vi, vi)   [dt folded]
    __shared__ u64 s_v01r[NDIM], s_v01n[NDIM];
    __shared__ u64 s_v10r[NDIM], s_v10n[NDIM];
    __shared__ u64 s_v11r[NDIM];                 // real only

    const int h   = blockIdx.y;
    const int tid = threadIdx.x;
    const float dt = expf(log_dt[h]);

    if (tid < NDIM) {
        const int idx = h * NDIM + tid;
        const float wr = w_re[idx] * dt, wi = w_im[idx] * dt;
        const float ar = -wr;
        s_arwi[tid]  = pk(ar, wi);
        s_armwi[tid] = pk(ar, -wi);
        s_wipm[tid]  = pk(-wi, wi);
        s_ar2[tid]   = pk(ar * ar, ar * ar);
        const float br = B_re[idx], bi = B_im[idx];
        const float cr = C_re[idx], ci = C_im[idx];
        const float pr = p_re[idx], pi = p_im[idx];
        const float v00r = dt * (br * cr - bi * ci), v00i = dt * (br * ci + bi * cr);
        const float v01r = dt * (br * pr + bi * pi), v01i = dt * (bi * pr - br * pi);
        const float v10r = dt * (pr * cr - pi * ci), v10i = dt * (pr * ci + pi * cr);
        const float v11r = dt * (pr * pr + pi * pi);
        s_v00r[tid] = pk(v00r, v00r); s_v00n[tid] = pk(-v00i, v00i);
        s_v01r[tid] = pk(v01r, v01r); s_v01n[tid] = pk(-v01i, v01i);
        s_v10r[tid] = pk(v10r, v10r); s_v10n[tid] = pk(-v10i, v10i);
        s_v11r[tid] = pk(v11r, v11r);
    }
    __syncthreads();

    const int l0 = blockIdx.x * 512 + tid;   // and l0 + 256

    float yv[2]; u64 y0m[2], ypp[2];
    #pragma unroll
    for (int j = 0; j < 2; j++) {
        const float yy = 2.0f * tanf((float)(l0 + 256 * j) * (float)(M_PI / (double)LLEN));
        yv[j] = yy; y0m[j] = pk(0.f, -yy); ypp[j] = pk(yy, yy);
    }

    const u64 NEG1 = pk(-1.f, -1.f);
    u64 r00[2] = {0ull, 0ull}, r01[2] = {0ull, 0ull};
    u64 r10[2] = {0ull, 0ull}, r11[2] = {0ull, 0ull};

    #pragma unroll 4
    for (int n = 0; n < NDIM; n++) {
        const u64 a1 = s_arwi[n], a2 = s_armwi[n], wp = s_wipm[n], q2 = s_ar2[n];
        const u64 v0r = s_v00r[n], v0n = s_v00n[n];
        const u64 v1r = s_v01r[n], v1n = s_v01n[n];
        const u64 v2r = s_v10r[n], v2n = s_v10n[n];
        const u64 v3r = s_v11r[n];
        #pragma unroll
        for (int j = 0; j < 2; j++) {
            const u64 n1  = f2add(a1, y0m[j]);        // (ar, -ai1)
            const u64 n2  = f2add(a2, y0m[j]);        // (ar, -ai2)
            const u64 A   = f2add(wp, ypp[j]);        // (ai1, ai2)
            const u64 den = f2fma(A, A, q2);          // |.|^2 pair
            float de1, de2; upk(de1, de2, den);
            const float i1 = __frcp_rn(de1), i2 = __frcp_rn(de2);
            const u64 d1 = f2mul(n1, pk(i1, i1));     // 1/(z - wdt)
            const u64 e  = f2mul(n2, pk(i2, i2));     // 1/(z - conj(wdt))
            const u64 s  = f2add(d1, e);              // (sr, si)
            const u64 t  = f2fma(e, NEG1, d1);        // (tr, ti)
            float tr, ti; upk(tr, ti, t);
            const u64 ts = pk(ti, tr);                // lane-swapped t
            // (re,im) += vr*(sr,si) + (-vi,vi)*(ti,tr)
            r00[j] = f2fma(v0r, s, r00[j]);  r00[j] = f2fma(v0n, ts, r00[j]);
            r01[j] = f2fma(v1r, s, r01[j]);  r01[j] = f2fma(v1n, ts, r01[j]);
            r10[j] = f2fma(v2r, s, r10[j]);  r10[j] = f2fma(v2n, ts, r10[j]);
            r11[j] = f2fma(v3r, s, r11[j]);
        }
    }

    #pragma unroll
    for (int j = 0; j < 2; j++) {
        float r00r, r00i, r01r, r01i, r10r, r10i, r11r, r11i;
        upk(r00r, r00i, r00[j]); upk(r01r, r01i, r01[j]);
        upk(r10r, r10i, r10[j]); upk(r11r, r11i, r11[j]);

        const float dr = 1.f + r11r, di = r11i;
        const float dinv = __frcp_rn(dr * dr + di * di);
        const float qr = r01r * r10r - r01i * r10i;
        const float qi = r01r * r10i + r01i * r10r;
        const float cr2 = (qr * dr + qi * di) * dinv;
        const float ci2 = (qi * dr - qr * di) * dinv;
        const float kr = r00r - cr2, ki = r00i - ci2;

        const float hy = 0.5f * yv[j];
        g_kf[h * LF + l0 + 256 * j] = make_float2(kr - hy * ki, ki + hy * kr);
    }

    if (blockIdx.x == 0 && tid == 0) {
        // Analytic Nyquist limit: k_f = Re(sum_n dt*B*C)
        float acc = 0.f;
        #pragma unroll
        for (int n = 0; n < NDIM; n++) { float a, b; upk(a, b, s_v00r[n]); acc += a; }
        g_kf[h * LF + LLEN / 2] = make_float2(acc, 0.f);
    }
}

// ---------------------------------------------------------------------------
// Kernel 2: per-head 4096-point inverse FFT, radix-4 DIT (6 stages),
// 512 threads/block for full-occupancy latency hiding.
// ---------------------------------------------------------------------------
__global__ void __launch_bounds__(512) ifft_kernel(float* __restrict__ out) {
    __shared__ float2 X[LLEN];       // 32 KB
    __shared__ float2 TW[1024];      // 8 KB : W^j = e^{+2*pi*i*j/4096}

    const int h   = blockIdx.x;
    const int tid = threadIdx.x;

    for (int j = tid; j < 1024; j += 512) {
        float s, c;
        sincosf((float)j * (float)(2.0 * M_PI / (double)LLEN), &s, &c);
        TW[j] = make_float2(c, s);
    }

    const float2* kf = &g_kf[h * LF];
    for (int idx = tid; idx < LLEN; idx += 512) {
        float2 v;
        if (idx <= LLEN / 2) {
            v = kf[idx];
        } else {
            const float2 t = kf[LLEN - idx];
            v = make_float2(t.x, -t.y);
        }
        int r = __brev((unsigned)idx) >> 20;            // 12-bit bit-reverse
        r = ((r & 0x555) << 1) | ((r >> 1) & 0x555);    // base-4 digit reverse
        X[r] = v;
    }
    __syncthreads();

    #pragma unroll
    for (int s = 0; s < 6; s++) {
        const int m    = 1 << (2 * s);
        const int step = 1024 >> (2 * s);
        for (int j = tid; j < 1024; j += 512) {
            const int k    = j & (m - 1);
            const int base = ((j >> (2 * s)) << (2 * s + 2)) + k;
            const float2 t0 = X[base];
            const float2 x1 = X[base + m], x2 = X[base + 2 * m], x3 = X[base + 3 * m];

            const int e1 = k * step;
            const float2 w1 = TW[e1];
            float2 w2; { const int e = 2 * e1; const float2 q = TW[e & 1023];
                         w2 = (e & 1024) ? make_float2(-q.y, q.x) : q; }
            float2 w3; { const int e = 3 * e1; const float2 q = TW[e & 1023];
                         const int qq = e >> 10;
                         w3 = (qq == 0) ? q : (qq == 1) ? make_float2(-q.y, q.x)
                                                        : make_float2(-q.x, -q.y); }

            const float2 t1 = make_float2(x1.x * w1.x - x1.y * w1.y, x1.x * w1.y + x1.y * w1.x);
            const float2 t2 = make_float2(x2.x * w2.x - x2.y * w2.y, x2.x * w2.y + x2.y * w2.x);
            const float2 t3 = make_float2(x3.x * w3.x - x3.y * w3.y, x3.x * w3.y + x3.y * w3.x);

            const float ax = t0.x + t2.x, ay = t0.y + t2.y;
            const float bx = t0.x - t2.x, by = t0.y - t2.y;
            const float cx = t1.x + t3.x, cy = t1.y + t3.y;
            const float dx = -(t1.y - t3.y), dy = t1.x - t3.x;

            X[base]         = make_float2(ax + cx, ay + cy);
            X[base + m]     = make_float2(bx + dx, by + dy);
            X[base + 2 * m] = make_float2(ax - cx, ay - cy);
            X[base + 3 * m] = make_float2(bx - dx, by - dy);
        }
        __syncthreads();
    }

    const float scale = 1.0f / (float)LLEN;
    for (int t = tid; t < LLEN; t += 512)
        out[h * LLEN + t] = X[t].x * scale;
}

extern "C" void kernel_launch(void* const* d_in, const int* in_sizes, int n_in,
                              void* d_out, int out_size) {
    const float* w_re   = (const float*)d_in[0];
    const float* w_im   = (const float*)d_in[1];
    const float* p_re   = (const float*)d_in[2];
    const float* p_im   = (const float*)d_in[3];
    const float* B_re   = (const float*)d_in[4];
    const float* B_im   = (const float*)d_in[5];
    const float* C_re   = (const float*)d_in[6];
    const float* C_im   = (const float*)d_in[7];
    const float* log_dt = (const float*)d_in[8];
    float* out = (float*)d_out;

    dim3 g1(4, HDIM);
    cauchy_kernel<<<g1, 256>>>(w_re, w_im, p_re, p_im, B_re, B_im, C_re, C_im, log_dt);
    ifft_kernel<<<HDIM, 512>>>(out);
}

// round 7
// speedup vs baseline: 1.9051x; 1.5470x over previous
#include <cuda_runtime.h>
#include <cuda_bf16.h>
#include <math.h>

#define HDIM 512
#define NDIM 32
#define LLEN 4096
#define LF   2049   // LLEN/2 + 1

__device__ float2 g_kf[HDIM * LF];

// ---------------- packed f32x2 helpers --------------------------------------
typedef unsigned long long u64;
__device__ __forceinline__ u64 pk(float lo, float hi) {
    u64 r; asm("mov.b64 %0,{%1,%2};" : "=l"(r) : "f"(lo), "f"(hi)); return r;
}
__device__ __forceinline__ void upk(float& lo, float& hi, u64 v) {
    asm("mov.b64 {%0,%1},%2;" : "=f"(lo), "=f"(hi) : "l"(v));
}
__device__ __forceinline__ u64 f2fma(u64 a, u64 b, u64 c) {
    u64 d; asm("fma.rn.f32x2 %0,%1,%2,%3;" : "=l"(d) : "l"(a), "l"(b), "l"(c)); return d;
}

// ---------------------------------------------------------------------------
// Kernel 1: Cauchy + Woodbury + bilinear.
// Identity: v/(z-w) + conj(v)/(z-conj(w)) = (alpha + i*beta*y) * g
//   alpha = -2*Re(v*conj(w)),  beta = 2*Re(v)   (REAL constants per n,row)
//   g = 1/D,  D = (|w|^2 - y^2) - i*(2*wr)*y,   z = i*y
// Accumulate ACC1 = sum (alpha,beta)*gr,  ACC2 = sum (alpha,beta)*gi  (f32x2)
//   re = ACC1.lo - y*ACC2.hi ;  im = ACC2.lo + y*ACC1.hi
// Each thread: two l values (l, l+256). Grid (4, HDIM) x 256.
// ---------------------------------------------------------------------------
__global__ void cauchy_kernel(const float* __restrict__ w_re, const float* __restrict__ w_im,
                              const float* __restrict__ p_re, const float* __restrict__ p_im,
                              const float* __restrict__ B_re, const float* __restrict__ B_im,
                              const float* __restrict__ C_re, const float* __restrict__ C_im,
                              const float* __restrict__ log_dt) {
    __shared__ u64 s_Mc[NDIM];                    // (|w|^2, -2*wr)
    __shared__ u64 s_ab00[NDIM], s_ab01[NDIM];    // (alpha, beta) per row
    __shared__ u64 s_ab10[NDIM], s_ab11[NDIM];
    __shared__ float s_ny[NDIM];                  // v00r for Nyquist limit

    const int h   = blockIdx.y;
    const int tid = threadIdx.x;
    const float dt = expf(log_dt[h]);

    if (tid < NDIM) {
        const int idx = h * NDIM + tid;
        const float wr = w_re[idx] * dt, wi = w_im[idx] * dt;
        s_Mc[tid] = pk(wr * wr + wi * wi, -2.0f * wr);
        const float br = B_re[idx], bi = B_im[idx];
        const float cr = C_re[idx], ci = C_im[idx];
        const float pr = p_re[idx], pi = p_im[idx];
        const float v00r = dt * (br * cr - bi * ci), v00i = dt * (br * ci + bi * cr);
        const float v01r = dt * (br * pr + bi * pi), v01i = dt * (bi * pr - br * pi);
        const float v10r = dt * (pr * cr - pi * ci), v10i = dt * (pr * ci + pi * cr);
        const float v11r = dt * (pr * pr + pi * pi);
        s_ab00[tid] = pk(-2.f * (v00r * wr + v00i * wi), 2.f * v00r);
        s_ab01[tid] = pk(-2.f * (v01r * wr + v01i * wi), 2.f * v01r);
        s_ab10[tid] = pk(-2.f * (v10r * wr + v10i * wi), 2.f * v10r);
        s_ab11[tid] = pk(-2.f * (v11r * wr),             2.f * v11r);
        s_ny[tid]   = v00r;
    }
    __syncthreads();

    const int l0 = blockIdx.x * 512 + tid;   // and l0 + 256

    float yv[2], y2[2];
    #pragma unroll
    for (int j = 0; j < 2; j++) {
        const float yy = 2.0f * tanf((float)(l0 + 256 * j) * (float)(M_PI / (double)LLEN));
        yv[j] = yy; y2[j] = yy * yy;
    }

    u64 a1_00[2] = {0,0}, a2_00[2] = {0,0};
    u64 a1_01[2] = {0,0}, a2_01[2] = {0,0};
    u64 a1_10[2] = {0,0}, a2_10[2] = {0,0};
    u64 a1_11[2] = {0,0}, a2_11[2] = {0,0};

    #pragma unroll 4
    for (int n = 0; n < NDIM; n++) {
        float M, c; upk(M, c, s_Mc[n]);
        const u64 ab0 = s_ab00[n], ab1 = s_ab01[n], ab2 = s_ab10[n], ab3 = s_ab11[n];
        #pragma unroll
        for (int j = 0; j < 2; j++) {
            const float Dr  = M - y2[j];
            const float Di  = c * yv[j];
            const float den = fmaf(Di, Di, Dr * Dr);
            const float inv = __frcp_rn(den);
            const float gr  = Dr * inv;
            const float gi  = -Di * inv;
            const u64 gg = pk(gr, gr), hh = pk(gi, gi);
            a1_00[j] = f2fma(ab0, gg, a1_00[j]);  a2_00[j] = f2fma(ab0, hh, a2_00[j]);
            a1_01[j] = f2fma(ab1, gg, a1_01[j]);  a2_01[j] = f2fma(ab1, hh, a2_01[j]);
            a1_10[j] = f2fma(ab2, gg, a1_10[j]);  a2_10[j] = f2fma(ab2, hh, a2_10[j]);
            a1_11[j] = f2fma(ab3, gg, a1_11[j]);  a2_11[j] = f2fma(ab3, hh, a2_11[j]);
        }
    }

    #pragma unroll
    for (int j = 0; j < 2; j++) {
        const float y = yv[j];
        float g00, b00, i00, q00; upk(g00, b00, a1_00[j]); upk(i00, q00, a2_00[j]);
        float g01, b01, i01, q01; upk(g01, b01, a1_01[j]); upk(i01, q01, a2_01[j]);
        float g10, b10, i10, q10; upk(g10, b10, a1_10[j]); upk(i10, q10, a2_10[j]);
        float g11, b11, i11, q11; upk(g11, b11, a1_11[j]); upk(i11, q11, a2_11[j]);
        const float r00r = g00 - y * q00, r00i = i00 + y * b00;
        const float r01r = g01 - y * q01, r01i = i01 + y * b01;
        const float r10r = g10 - y * q10, r10i = i10 + y * b10;
        const float r11r = g11 - y * q11, r11i = i11 + y * b11;

        // Woodbury: k = r00 - r01*r10/(1+r11)
        const float dr = 1.f + r11r, di = r11i;
        const float dinv = __frcp_rn(dr * dr + di * di);
        const float qr = r01r * r10r - r01i * r10i;
        const float qi = r01r * r10i + r01i * r10r;
        const float cr2 = (qr * dr + qi * di) * dinv;
        const float ci2 = (qi * dr - qr * di) * dinv;
        const float kr = r00r - cr2, ki = r00i - ci2;

        // scale by 2/(1+omega) = 1 + i*(y/2)
        const float hy = 0.5f * y;
        g_kf[h * LF + l0 + 256 * j] = make_float2(kr - hy * ki, ki + hy * kr);
    }

    if (blockIdx.x == 0 && tid == 0) {
        float acc = 0.f;
        #pragma unroll
        for (int n = 0; n < NDIM; n++) acc += s_ny[n];
        g_kf[h * LF + LLEN / 2] = make_float2(acc, 0.f);
    }
}

// ---------------------------------------------------------------------------
// Kernel 2: per-head 4096-pt inverse FFT, radix-4 DIT, XOR bank swizzle,
// w2/w3 computed from w1, last stage fused into the gmem store.
// ---------------------------------------------------------------------------
#define IX(i) ((i) ^ (((i) >> 4) & 15))

__global__ void __launch_bounds__(512) ifft_kernel(float* __restrict__ out) {
    __shared__ float2 X[LLEN];       // 32 KB (swizzled)
    __shared__ float2 TW[1024];      // 8 KB  (swizzled): W^j = e^{+2*pi*i*j/4096}

    const int h   = blockIdx.x;
    const int tid = threadIdx.x;

    for (int j = tid; j < 1024; j += 512) {
        float s, c;
        sincosf((float)j * (float)(2.0 * M_PI / (double)LLEN), &s, &c);
        TW[IX(j)] = make_float2(c, s);
    }

    const float2* kf = &g_kf[h * LF];
    for (int idx = tid; idx < LLEN; idx += 512) {
        float2 v;
        if (idx <= LLEN / 2) {
            v = kf[idx];
        } else {
            const float2 t = kf[LLEN - idx];
            v = make_float2(t.x, -t.y);
        }
        int r = __brev((unsigned)idx) >> 20;            // 12-bit bit-reverse
        r = ((r & 0x555) << 1) | ((r >> 1) & 0x555);    // base-4 digit reverse
        X[IX(r)] = v;
    }
    __syncthreads();

    // stages 0..4 in shared memory
    #pragma unroll
    for (int s = 0; s < 5; s++) {
        const int m    = 1 << (2 * s);
        const int step = 1024 >> (2 * s);
        #pragma unroll 2
        for (int j = tid; j < 1024; j += 512) {
            const int k    = j & (m - 1);
            const int base = ((j >> (2 * s)) << (2 * s + 2)) + k;
            const float2 t0 = X[IX(base)];
            const float2 x1 = X[IX(base + m)];
            const float2 x2 = X[IX(base + 2 * m)];
            const float2 x3 = X[IX(base + 3 * m)];

            const float2 w1 = TW[IX(k * step)];
            const float2 w2 = make_float2(w1.x * w1.x - w1.y * w1.y, 2.f * w1.x * w1.y);
            const float2 w3 = make_float2(w1.x * w2.x - w1.y * w2.y, w1.x * w2.y + w1.y * w2.x);

            const float2 t1 = make_float2(x1.x * w1.x - x1.y * w1.y, x1.x * w1.y + x1.y * w1.x);
            const float2 t2 = make_float2(x2.x * w2.x - x2.y * w2.y, x2.x * w2.y + x2.y * w2.x);
            const float2 t3 = make_float2(x3.x * w3.x - x3.y * w3.y, x3.x * w3.y + x3.y * w3.x);

            const float ax = t0.x + t2.x, ay = t0.y + t2.y;
            const float bx = t0.x - t2.x, by = t0.y - t2.y;
            const float cx = t1.x + t3.x, cy = t1.y + t3.y;
            const float dx = -(t1.y - t3.y), dy = t1.x - t3.x;

            X[IX(base)]         = make_float2(ax + cx, ay + cy);
            X[IX(base + m)]     = make_float2(bx + dx, by + dy);
            X[IX(base + 2 * m)] = make_float2(ax - cx, ay - cy);
            X[IX(base + 3 * m)] = make_float2(bx - dx, by - dy);
        }
        __syncthreads();
    }

    // stage 5 (m=1024) fused into the output store: only real parts needed
    const float scale = 1.0f / (float)LLEN;
    float* o = out + h * LLEN;
    #pragma unroll 2
    for (int j = tid; j < 1024; j += 512) {
        const int k = j;                       // m=1024: base = k
        const float2 t0 = X[IX(k)];
        const float2 x1 = X[IX(k + 1024)];
        const float2 x2 = X[IX(k + 2048)];
        const float2 x3 = X[IX(k + 3072)];

        const float2 w1 = TW[IX(k)];
        const float2 w2 = make_float2(w1.x * w1.x - w1.y * w1.y, 2.f * w1.x * w1.y);
        const float2 w3 = make_float2(w1.x * w2.x - w1.y * w2.y, w1.x * w2.y + w1.y * w2.x);

        const float2 t1 = make_float2(x1.x * w1.x - x1.y * w1.y, x1.x * w1.y + x1.y * w1.x);
        const float2 t2 = make_float2(x2.x * w2.x - x2.y * w2.y, x2.x * w2.y + x2.y * w2.x);
        const float2 t3 = make_float2(x3.x * w3.x - x3.y * w3.y, x3.x * w3.y + x3.y * w3.x);

        const float ax = t0.x + t2.x;
        const float bx = t0.x - t2.x;
        const float cx = t1.x + t3.x;
        const float dx = -(t1.y - t3.y);

        o[k]        = (ax + cx) * scale;
        o[k + 1024] = (bx + dx) * scale;
        o[k + 2048] = (ax - cx) * scale;
        o[k + 3072] = (bx - dx) * scale;
    }
}

extern "C" void kernel_launch(void* const* d_in, const int* in_sizes, int n_in,
                              void* d_out, int out_size) {
    const float* w_re   = (const float*)d_in[0];
    const float* w_im   = (const float*)d_in[1];
    const float* p_re   = (const float*)d_in[2];
    const float* p_im   = (const float*)d_in[3];
    const float* B_re   = (const float*)d_in[4];
    const float* B_im   = (const float*)d_in[5];
    const float* C_re   = (const float*)d_in[6];
    const float* C_im   = (const float*)d_in[7];
    const float* log_dt = (const float*)d_in[8];
    float* out = (float*)d_out;

    dim3 g1(4, HDIM);
    cauchy_kernel<<<g1, 256>>>(w_re, w_im, p_re, p_im, B_re, B_im, C_re, C_im, log_dt);
    ifft_kernel<<<HDIM, 512>>>(out);
}

// round 8
// speedup vs baseline: 2.0205x; 1.0606x over previous
#include <cuda_runtime.h>
#include <cuda_bf16.h>
#include <math.h>

#define HDIM 512
#define NDIM 32
#define LLEN 4096
#define LF   2049   // LLEN/2 + 1

__device__ float2 g_kf[HDIM * LF];
__device__ float2 g_tw[1024];      // W^j = e^{+2*pi*i*j/4096}, j < 1024

// ---------------- packed f32x2 + fast-rcp helpers ---------------------------
typedef unsigned long long u64;
__device__ __forceinline__ u64 pk(float lo, float hi) {
    u64 r; asm("mov.b64 %0,{%1,%2};" : "=l"(r) : "f"(lo), "f"(hi)); return r;
}
__device__ __forceinline__ void upk(float& lo, float& hi, u64 v) {
    asm("mov.b64 {%0,%1},%2;" : "=f"(lo), "=f"(hi) : "l"(v));
}
__device__ __forceinline__ u64 f2fma(u64 a, u64 b, u64 c) {
    u64 d; asm("fma.rn.f32x2 %0,%1,%2,%3;" : "=l"(d) : "l"(a), "l"(b), "l"(c)); return d;
}
__device__ __forceinline__ float frcp(float x) {        // single MUFU.RCP, ~2ulp
    float r; asm("rcp.approx.f32 %0,%1;" : "=f"(r) : "f"(x)); return r;
}

// ---------------------------------------------------------------------------
// Kernel 0: one-time twiddle table (one block)
// ---------------------------------------------------------------------------
__global__ void twiddle_kernel() {
    const int j = threadIdx.x + blockIdx.x * blockDim.x;
    if (j < 1024) {
        float s, c;
        sincosf((float)j * (float)(2.0 * M_PI / (double)LLEN), &s, &c);
        g_tw[j] = make_float2(c, s);
    }
}

// ---------------------------------------------------------------------------
// Kernel 1: Cauchy + Woodbury + bilinear.
// v/(z-w) + conj(v)/(z-conj(w)) = (alpha + i*beta*y) * g
//   alpha = -2*Re(v*conj(w)), beta = 2*Re(v)  (real per n,row)
//   g = 1/D, D = (|w|^2 - y^2) - i*(2*wr)*y,  z = i*y
// ---------------------------------------------------------------------------
__global__ void cauchy_kernel(const float* __restrict__ w_re, const float* __restrict__ w_im,
                              const float* __restrict__ p_re, const float* __restrict__ p_im,
                              const float* __restrict__ B_re, const float* __restrict__ B_im,
                              const float* __restrict__ C_re, const float* __restrict__ C_im,
                              const float* __restrict__ log_dt) {
    __shared__ u64 s_Mc[NDIM];                    // (|w|^2, -2*wr)
    __shared__ u64 s_ab00[NDIM], s_ab01[NDIM];    // (alpha, beta) per row
    __shared__ u64 s_ab10[NDIM], s_ab11[NDIM];
    __shared__ float s_ny[NDIM];                  // v00r for Nyquist limit

    const int h   = blockIdx.y;
    const int tid = threadIdx.x;
    const float dt = expf(log_dt[h]);

    if (tid < NDIM) {
        const int idx = h * NDIM + tid;
        const float wr = w_re[idx] * dt, wi = w_im[idx] * dt;
        s_Mc[tid] = pk(wr * wr + wi * wi, -2.0f * wr);
        const float br = B_re[idx], bi = B_im[idx];
        const float cr = C_re[idx], ci = C_im[idx];
        const float pr = p_re[idx], pi = p_im[idx];
        const float v00r = dt * (br * cr - bi * ci), v00i = dt * (br * ci + bi * cr);
        const float v01r = dt * (br * pr + bi * pi), v01i = dt * (bi * pr - br * pi);
        const float v10r = dt * (pr * cr - pi * ci), v10i = dt * (pr * ci + pi * cr);
        const float v11r = dt * (pr * pr + pi * pi);
        s_ab00[tid] = pk(-2.f * (v00r * wr + v00i * wi), 2.f * v00r);
        s_ab01[tid] = pk(-2.f * (v01r * wr + v01i * wi), 2.f * v01r);
        s_ab10[tid] = pk(-2.f * (v10r * wr + v10i * wi), 2.f * v10r);
        s_ab11[tid] = pk(-2.f * (v11r * wr),             2.f * v11r);
        s_ny[tid]   = v00r;
    }
    __syncthreads();

    const int l0 = blockIdx.x * 512 + tid;   // and l0 + 256

    float yv[2], y2[2];
    #pragma unroll
    for (int j = 0; j < 2; j++) {
        const float yy = 2.0f * tanf((float)(l0 + 256 * j) * (float)(M_PI / (double)LLEN));
        yv[j] = yy; y2[j] = yy * yy;
    }

    u64 a1_00[2] = {0,0}, a2_00[2] = {0,0};
    u64 a1_01[2] = {0,0}, a2_01[2] = {0,0};
    u64 a1_10[2] = {0,0}, a2_10[2] = {0,0};
    u64 a1_11[2] = {0,0}, a2_11[2] = {0,0};

    #pragma unroll 4
    for (int n = 0; n < NDIM; n++) {
        float M, c; upk(M, c, s_Mc[n]);
        const u64 ab0 = s_ab00[n], ab1 = s_ab01[n], ab2 = s_ab10[n], ab3 = s_ab11[n];
        #pragma unroll
        for (int j = 0; j < 2; j++) {
            const float Dr  = M - y2[j];
            const float Di  = c * yv[j];
            const float den = fmaf(Di, Di, Dr * Dr);
            const float inv = frcp(den);
            const float gr  = Dr * inv;
            const float gi  = -Di * inv;
            const u64 gg = pk(gr, gr), hh = pk(gi, gi);
            a1_00[j] = f2fma(ab0, gg, a1_00[j]);  a2_00[j] = f2fma(ab0, hh, a2_00[j]);
            a1_01[j] = f2fma(ab1, gg, a1_01[j]);  a2_01[j] = f2fma(ab1, hh, a2_01[j]);
            a1_10[j] = f2fma(ab2, gg, a1_10[j]);  a2_10[j] = f2fma(ab2, hh, a2_10[j]);
            a1_11[j] = f2fma(ab3, gg, a1_11[j]);  a2_11[j] = f2fma(ab3, hh, a2_11[j]);
        }
    }

    #pragma unroll
    for (int j = 0; j < 2; j++) {
        const float y = yv[j];
        float g00, b00, i00, q00; upk(g00, b00, a1_00[j]); upk(i00, q00, a2_00[j]);
        float g01, b01, i01, q01; upk(g01, b01, a1_01[j]); upk(i01, q01, a2_01[j]);
        float g10, b10, i10, q10; upk(g10, b10, a1_10[j]); upk(i10, q10, a2_10[j]);
        float g11, b11, i11, q11; upk(g11, b11, a1_11[j]); upk(i11, q11, a2_11[j]);
        const float r00r = g00 - y * q00, r00i = i00 + y * b00;
        const float r01r = g01 - y * q01, r01i = i01 + y * b01;
        const float r10r = g10 - y * q10, r10i = i10 + y * b10;
        const float r11r = g11 - y * q11, r11i = i11 + y * b11;

        // Woodbury: k = r00 - r01*r10/(1+r11)
        const float dr = 1.f + r11r, di = r11i;
        const float dinv = frcp(fmaf(dr, dr, di * di));
        const float qr = r01r * r10r - r01i * r10i;
        const float qi = r01r * r10i + r01i * r10r;
        const float cr2 = (qr * dr + qi * di) * dinv;
        const float ci2 = (qi * dr - qr * di) * dinv;
        const float kr = r00r - cr2, ki = r00i - ci2;

        // scale by 2/(1+omega) = 1 + i*(y/2)
        const float hy = 0.5f * y;
        g_kf[h * LF + l0 + 256 * j] = make_float2(kr - hy * ki, ki + hy * kr);
    }

    if (blockIdx.x == 0 && tid == 0) {
        float acc = 0.f;
        #pragma unroll
        for (int n = 0; n < NDIM; n++) acc += s_ny[n];
        g_kf[h * LF + LLEN / 2] = make_float2(acc, 0.f);
    }
}

// ---------------------------------------------------------------------------
// Kernel 2: per-head 4096-pt inverse FFT, radix-4 DIT, XOR bank swizzle,
// w2/w3 computed from w1, last stage fused into the gmem store,
// twiddles loaded from g_tw (no per-block sincosf).
// ---------------------------------------------------------------------------
#define IX(i) ((i) ^ (((i) >> 4) & 15))

__global__ void __launch_bounds__(512) ifft_kernel(float* __restrict__ out) {
    __shared__ float2 X[LLEN];       // 32 KB (swizzled)
    __shared__ float2 TW[1024];      // 8 KB  (swizzled)

    const int h   = blockIdx.x;
    const int tid = threadIdx.x;

    #pragma unroll
    for (int j = tid; j < 1024; j += 512)
        TW[IX(j)] = g_tw[j];

    const float2* kf = &g_kf[h * LF];
    for (int idx = tid; idx < LLEN; idx += 512) {
        float2 v;
        if (idx <= LLEN / 2) {
            v = kf[idx];
        } else {
            const float2 t = kf[LLEN - idx];
            v = make_float2(t.x, -t.y);
        }
        int r = __brev((unsigned)idx) >> 20;            // 12-bit bit-reverse
        r = ((r & 0x555) << 1) | ((r >> 1) & 0x555);    // base-4 digit reverse
        X[IX(r)] = v;
    }
    __syncthreads();

    // stages 0..4 in shared memory
    #pragma unroll
    for (int s = 0; s < 5; s++) {
        const int m    = 1 << (2 * s);
        const int step = 1024 >> (2 * s);
        #pragma unroll 2
        for (int j = tid; j < 1024; j += 512) {
            const int k    = j & (m - 1);
            const int base = ((j >> (2 * s)) << (2 * s + 2)) + k;
            const float2 t0 = X[IX(base)];
            const float2 x1 = X[IX(base + m)];
            const float2 x2 = X[IX(base + 2 * m)];
            const float2 x3 = X[IX(base + 3 * m)];

            const float2 w1 = TW[IX(k * step)];
            const float2 w2 = make_float2(w1.x * w1.x - w1.y * w1.y, 2.f * w1.x * w1.y);
            const float2 w3 = make_float2(w1.x * w2.x - w1.y * w2.y, w1.x * w2.y + w1.y * w2.x);

            const float2 t1 = make_float2(x1.x * w1.x - x1.y * w1.y, x1.x * w1.y + x1.y * w1.x);
            const float2 t2 = make_float2(x2.x * w2.x - x2.y * w2.y, x2.x * w2.y + x2.y * w2.x);
            const float2 t3 = make_float2(x3.x * w3.x - x3.y * w3.y, x3.x * w3.y + x3.y * w3.x);

            const float ax = t0.x + t2.x, ay = t0.y + t2.y;
            const float bx = t0.x - t2.x, by = t0.y - t2.y;
            const float cx = t1.x + t3.x, cy = t1.y + t3.y;
            const float dx = -(t1.y - t3.y), dy = t1.x - t3.x;

            X[IX(base)]         = make_float2(ax + cx, ay + cy);
            X[IX(base + m)]     = make_float2(bx + dx, by + dy);
            X[IX(base + 2 * m)] = make_float2(ax - cx, ay - cy);
            X[IX(base + 3 * m)] = make_float2(bx - dx, by - dy);
        }
        __syncthreads();
    }

    // stage 5 (m=1024) fused into the output store: only real parts needed
    const float scale = 1.0f / (float)LLEN;
    float* o = out + h * LLEN;
    #pragma unroll 2
    for (int j = tid; j < 1024; j += 512) {
        const int k = j;
        const float2 t0 = X[IX(k)];
        const float2 x1 = X[IX(k + 1024)];
        const float2 x2 = X[IX(k + 2048)];
        const float2 x3 = X[IX(k + 3072)];

        const float2 w1 = TW[IX(k)];
        const float2 w2 = make_float2(w1.x * w1.x - w1.y * w1.y, 2.f * w1.x * w1.y);
        const float2 w3 = make_float2(w1.x * w2.x - w1.y * w2.y, w1.x * w2.y + w1.y * w2.x);

        const float2 t1 = make_float2(x1.x * w1.x - x1.y * w1.y, x1.x * w1.y + x1.y * w1.x);
        const float2 t2 = make_float2(x2.x * w2.x - x2.y * w2.y, x2.x * w2.y + x2.y * w2.x);
        const float2 t3 = make_float2(x3.x * w3.x - x3.y * w3.y, x3.x * w3.y + x3.y * w3.x);

        const float ax = t0.x + t2.x;
        const float bx = t0.x - t2.x;
        const float cx = t1.x + t3.x;
        const float dx = -(t1.y - t3.y);

        o[k]        = (ax + cx) * scale;
        o[k + 1024] = (bx + dx) * scale;
        o[k + 2048] = (ax - cx) * scale;
        o[k + 3072] = (bx - dx) * scale;
    }
}

extern "C" void kernel_launch(void* const* d_in, const int* in_sizes, int n_in,
                              void* d_out, int out_size) {
    const float* w_re   = (const float*)d_in[0];
    const float* w_im   = (const float*)d_in[1];
    const float* p_re   = (const float*)d_in[2];
    const float* p_im   = (const float*)d_in[3];
    const float* B_re   = (const float*)d_in[4];
    const float* B_im   = (const float*)d_in[5];
    const float* C_re   = (const float*)d_in[6];
    const float* C_im   = (const float*)d_in[7];
    const float* log_dt = (const float*)d_in[8];
    float* out = (float*)d_out;

    twiddle_kernel<<<2, 512>>>();
    dim3 g1(4, HDIM);
    cauchy_kernel<<<g1, 256>>>(w_re, w_im, p_re, p_im, B_re, B_im, C_re, C_im, log_dt);
    ifft_kernel<<<HDIM, 512>>>(out);
}

// round 9
// speedup vs baseline: 2.1718x; 1.0749x over previous
#include <cuda_runtime.h>
#include <cuda_bf16.h>
#include <math.h>

#define HDIM 512
#define NDIM 32
#define LLEN 4096
#define LF   2049   // LLEN/2 + 1

__device__ float2 g_kf[HDIM * LF];
__device__ float2 g_tw[1024];      // W^j = e^{+2*pi*i*j/4096}, j < 1024

// ---------------- packed f32x2 + fast-rcp helpers ---------------------------
typedef unsigned long long u64;
__device__ __forceinline__ u64 pk(float lo, float hi) {
    u64 r; asm("mov.b64 %0,{%1,%2};" : "=l"(r) : "f"(lo), "f"(hi)); return r;
}
__device__ __forceinline__ void upk(float& lo, float& hi, u64 v) {
    asm("mov.b64 {%0,%1},%2;" : "=f"(lo), "=f"(hi) : "l"(v));
}
__device__ __forceinline__ u64 f2add(u64 a, u64 b) {
    u64 d; asm("add.rn.f32x2 %0,%1,%2;" : "=l"(d) : "l"(a), "l"(b)); return d;
}
__device__ __forceinline__ u64 f2mul(u64 a, u64 b) {
    u64 d; asm("mul.rn.f32x2 %0,%1,%2;" : "=l"(d) : "l"(a), "l"(b)); return d;
}
__device__ __forceinline__ u64 f2fma(u64 a, u64 b, u64 c) {
    u64 d; asm("fma.rn.f32x2 %0,%1,%2,%3;" : "=l"(d) : "l"(a), "l"(b), "l"(c)); return d;
}
__device__ __forceinline__ float frcp(float x) {        // single MUFU.RCP
    float r; asm("rcp.approx.f32 %0,%1;" : "=f"(r) : "f"(x)); return r;
}

// ---------------------------------------------------------------------------
// Kernel 1: Cauchy + Woodbury + bilinear (+ twiddle table build on h==0 blocks)
// v/(z-w) + conj(v)/(z-conj(w)) = (alpha + i*beta*y) * g
//   alpha = -2*Re(v*conj(w)), beta = 2*Re(v)  (real per n,row)
//   g = 1/D, D = (|w|^2 - y^2) - i*(2*wr)*y,  z = i*y
// Accumulate a1 = sum (alpha,beta)*gr, a2 = sum (alpha,beta)*h  with h = -gi.
//   re = a1.lo + y*a2.hi ;  im = -a2.lo + y*a1.hi
// Scalar prologue packed across the thread's two l-values (j lanes).
// ---------------------------------------------------------------------------
__global__ void cauchy_kernel(const float* __restrict__ w_re, const float* __restrict__ w_im,
                              const float* __restrict__ p_re, const float* __restrict__ p_im,
                              const float* __restrict__ B_re, const float* __restrict__ B_im,
                              const float* __restrict__ C_re, const float* __restrict__ C_im,
                              const float* __restrict__ log_dt) {
    __shared__ u64 s_MM[NDIM], s_cc[NDIM];        // (|w|^2,|w|^2), (-2wr,-2wr)
    __shared__ u64 s_ab00[NDIM], s_ab01[NDIM];    // (alpha, beta) per row
    __shared__ u64 s_ab10[NDIM], s_ab11[NDIM];
    __shared__ float s_ny[NDIM];                  // v00r for Nyquist limit

    const int h   = blockIdx.y;
    const int tid = threadIdx.x;
    const float dt = expf(log_dt[h]);

    if (tid < NDIM) {
        const int idx = h * NDIM + tid;
        const float wr = w_re[idx] * dt, wi = w_im[idx] * dt;
        const float M = wr * wr + wi * wi, c = -2.0f * wr;
        s_MM[tid] = pk(M, M);
        s_cc[tid] = pk(c, c);
        const float br = B_re[idx], bi = B_im[idx];
        const float cr = C_re[idx], ci = C_im[idx];
        const float pr = p_re[idx], pi = p_im[idx];
        const float v00r = dt * (br * cr - bi * ci), v00i = dt * (br * ci + bi * cr);
        const float v01r = dt * (br * pr + bi * pi), v01i = dt * (bi * pr - br * pi);
        const float v10r = dt * (pr * cr - pi * ci), v10i = dt * (pr * ci + pi * cr);
        const float v11r = dt * (pr * pr + pi * pi);
        s_ab00[tid] = pk(-2.f * (v00r * wr + v00i * wi), 2.f * v00r);
        s_ab01[tid] = pk(-2.f * (v01r * wr + v01i * wi), 2.f * v01r);
        s_ab10[tid] = pk(-2.f * (v10r * wr + v10i * wi), 2.f * v10r);
        s_ab11[tid] = pk(-2.f * (v11r * wr),             2.f * v11r);
        s_ny[tid]   = v00r;
    }
    __syncthreads();

    const int l0 = blockIdx.x * 512 + tid;   // this thread: l0 and l0 + 256

    float yv[2];
    #pragma unroll
    for (int j = 0; j < 2; j++)
        yv[j] = 2.0f * tanf((float)(l0 + 256 * j) * (float)(M_PI / (double)LLEN));
    const u64 yP   = pk(yv[0], yv[1]);
    const u64 ny2P = pk(-yv[0] * yv[0], -yv[1] * yv[1]);

    u64 a1_00[2] = {0,0}, a2_00[2] = {0,0};
    u64 a1_01[2] = {0,0}, a2_01[2] = {0,0};
    u64 a1_10[2] = {0,0}, a2_10[2] = {0,0};
    u64 a1_11[2] = {0,0}, a2_11[2] = {0,0};

    #pragma unroll 4
    for (int n = 0; n < NDIM; n++) {
        const u64 DrP  = f2add(s_MM[n], ny2P);       // (Dr0, Dr1)
        const u64 DiP  = f2mul(s_cc[n], yP);         // (Di0, Di1)
        const u64 Dr2P = f2mul(DrP, DrP);
        const u64 denP = f2fma(DiP, DiP, Dr2P);
        float de0, de1; upk(de0, de1, denP);
        const u64 invP = pk(frcp(de0), frcp(de1));
        const u64 grP  = f2mul(DrP, invP);           // (gr0, gr1)
        const u64 hP   = f2mul(DiP, invP);           // h = -gi
        float gr0, gr1; upk(gr0, gr1, grP);
        float h0,  h1;  upk(h0,  h1,  hP);
        const u64 gg0 = pk(gr0, gr0), gg1 = pk(gr1, gr1);
        const u64 hh0 = pk(h0, h0),   hh1 = pk(h1, h1);
        const u64 ab0 = s_ab00[n], ab1 = s_ab01[n], ab2 = s_ab10[n], ab3 = s_ab11[n];
        a1_00[0] = f2fma(ab0, gg0, a1_00[0]);  a2_00[0] = f2fma(ab0, hh0, a2_00[0]);
        a1_01[0] = f2fma(ab1, gg0, a1_01[0]);  a2_01[0] = f2fma(ab1, hh0, a2_01[0]);
        a1_10[0] = f2fma(ab2, gg0, a1_10[0]);  a2_10[0] = f2fma(ab2, hh0, a2_10[0]);
        a1_11[0] = f2fma(ab3, gg0, a1_11[0]);  a2_11[0] = f2fma(ab3, hh0, a2_11[0]);
        a1_00[1] = f2fma(ab0, gg1, a1_00[1]);  a2_00[1] = f2fma(ab0, hh1, a2_00[1]);
        a1_01[1] = f2fma(ab1, gg1, a1_01[1]);  a2_01[1] = f2fma(ab1, hh1, a2_01[1]);
        a1_10[1] = f2fma(ab2, gg1, a1_10[1]);  a2_10[1] = f2fma(ab2, hh1, a2_10[1]);
        a1_11[1] = f2fma(ab3, gg1, a1_11[1]);  a2_11[1] = f2fma(ab3, hh1, a2_11[1]);
    }

    #pragma unroll
    for (int j = 0; j < 2; j++) {
        const float y = yv[j];
        // re = a1.lo + y*a2.hi ; im = -a2.lo + y*a1.hi
        float g00, b00, i00, q00; upk(g00, b00, a1_00[j]); upk(i00, q00, a2_00[j]);
        float g01, b01, i01, q01; upk(g01, b01, a1_01[j]); upk(i01, q01, a2_01[j]);
        float g10, b10, i10, q10; upk(g10, b10, a1_10[j]); upk(i10, q10, a2_10[j]);
        float g11, b11, i11, q11; upk(g11, b11, a1_11[j]); upk(i11, q11, a2_11[j]);
        const float r00r = g00 + y * q00, r00i = -i00 + y * b00;
        const float r01r = g01 + y * q01, r01i = -i01 + y * b01;
        const float r10r = g10 + y * q10, r10i = -i10 + y * b10;
        const float r11r = g11 + y * q11, r11i = -i11 + y * b11;

        // Woodbury: k = r00 - r01*r10/(1+r11)
        const float dr = 1.f + r11r, di = r11i;
        const float dinv = frcp(fmaf(dr, dr, di * di));
        const float qr = r01r * r10r - r01i * r10i;
        const float qi = r01r * r10i + r01i * r10r;
        const float cr2 = (qr * dr + qi * di) * dinv;
        const float ci2 = (qi * dr - qr * di) * dinv;
        const float kr = r00r - cr2, ki = r00i - ci2;

        // scale by 2/(1+omega) = 1 + i*(y/2)
        const float hy = 0.5f * y;
        g_kf[h * LF + l0 + 256 * j] = make_float2(kr - hy * ki, ki + hy * kr);
    }

    if (blockIdx.x == 0 && tid == 0) {
        float acc = 0.f;
        #pragma unroll
        for (int n = 0; n < NDIM; n++) acc += s_ny[n];
        g_kf[h * LF + LLEN / 2] = make_float2(acc, 0.f);
    }

    // twiddle table: h==0 blocks (4 x 256 threads = 1024 entries), hidden
    // under the other 2044 blocks' work
    if (blockIdx.y == 0) {
        const int j = blockIdx.x * 256 + tid;
        float s, c;
        sincosf((float)j * (float)(2.0 * M_PI / (double)LLEN), &s, &c);
        g_tw[j] = make_float2(c, s);
    }
}

// ---------------------------------------------------------------------------
// Kernel 2: per-head 4096-pt inverse FFT, radix-4 DIT.
// Stage 0 (unity twiddles) fused into the gmem load; stage 5 fused into the
// gmem store. Stages 1..4 in smem with XOR bank swizzle; w2/w3 from w1.
// ---------------------------------------------------------------------------
#define IX(i) ((i) ^ (((i) >> 4) & 15))

__global__ void __launch_bounds__(512) ifft_kernel(float* __restrict__ out) {
    __shared__ float2 X[LLEN];       // 32 KB (swizzled)
    __shared__ float2 TW[1024];      // 8 KB  (swizzled)

    const int h   = blockIdx.x;
    const int tid = threadIdx.x;

    #pragma unroll
    for (int j = tid; j < 1024; j += 512)
        TW[IX(j)] = g_tw[j];

    // fused digit-reversal load + stage 0 (twiddle-free radix-4)
    const float2* kf = &g_kf[h * LF];
    #pragma unroll 2
    for (int j = tid; j < 1024; j += 512) {
        const int br = __brev((unsigned)j) >> 22;                 // 10-bit reverse
        const int rj = ((br & 0x155) << 1) | ((br >> 1) & 0x155); // base-4 digit rev
        const float2 t0 = kf[rj];
        const float2 t1 = kf[1024 + rj];
        const float2 c2 = kf[2048 - rj];  const float2 t2 = make_float2(c2.x, -c2.y);
        const float2 c3 = kf[1024 - rj];  const float2 t3 = make_float2(c3.x, -c3.y);

        const float ax = t0.x + t2.x, ay = t0.y + t2.y;
        const float bx = t0.x - t2.x, by = t0.y - t2.y;
        const float cx = t1.x + t3.x, cy = t1.y + t3.y;
        const float dx = -(t1.y - t3.y), dy = t1.x - t3.x;

        const int base = 4 * j;
        X[IX(base)]     = make_float2(ax + cx, ay + cy);
        X[IX(base + 1)] = make_float2(bx + dx, by + dy);
        X[IX(base + 2)] = make_float2(ax - cx, ay - cy);
        X[IX(base + 3)] = make_float2(bx - dx, by - dy);
    }
    __syncthreads();

    // stages 1..4 in shared memory
    #pragma unroll
    for (int s = 1; s < 5; s++) {
        const int m    = 1 << (2 * s);
        const int step = 1024 >> (2 * s);
        #pragma unroll 2
        for (int j = tid; j < 1024; j += 512) {
            const int k    = j & (m - 1);
            const int base = ((j >> (2 * s)) << (2 * s + 2)) + k;
            const float2 t0 = X[IX(base)];
            const float2 x1 = X[IX(base + m)];
            const float2 x2 = X[IX(base + 2 * m)];
            const float2 x3 = X[IX(base + 3 * m)];

            const float2 w1 = TW[IX(k * step)];
            const float2 w2 = make_float2(w1.x * w1.x - w1.y * w1.y, 2.f * w1.x * w1.y);
            const float2 w3 = make_float2(w1.x * w2.x - w1.y * w2.y, w1.x * w2.y + w1.y * w2.x);

            const float2 t1 = make_float2(x1.x * w1.x - x1.y * w1.y, x1.x * w1.y + x1.y * w1.x);
            const float2 t2 = make_float2(x2.x * w2.x - x2.y * w2.y, x2.x * w2.y + x2.y * w2.x);
            const float2 t3 = make_float2(x3.x * w3.x - x3.y * w3.y, x3.x * w3.y + x3.y * w3.x);

            const float ax = t0.x + t2.x, ay = t0.y + t2.y;
            const float bx = t0.x - t2.x, by = t0.y - t2.y;
            const float cx = t1.x + t3.x, cy = t1.y + t3.y;
            const float dx = -(t1.y - t3.y), dy = t1.x - t3.x;

            X[IX(base)]         = make_float2(ax + cx, ay + cy);
            X[IX(base + m)]     = make_float2(bx + dx, by + dy);
            X[IX(base + 2 * m)] = make_float2(ax - cx, ay - cy);
            X[IX(base + 3 * m)] = make_float2(bx - dx, by - dy);
        }
        __syncthreads();
    }

    // stage 5 (m=1024) fused into the output store: only real parts needed
    const float scale = 1.0f / (float)LLEN;
    float* o = out + h * LLEN;
    #pragma unroll 2
    for (int j = tid; j < 1024; j += 512) {
        const int k = j;
        const float2 t0 = X[IX(k)];
        const float2 x1 = X[IX(k + 1024)];
        const float2 x2 = X[IX(k + 2048)];
        const float2 x3 = X[IX(k + 3072)];

        const float2 w1 = TW[IX(k)];
        const float2 w2 = make_float2(w1.x * w1.x - w1.y * w1.y, 2.f * w1.x * w1.y);
        const float2 w3 = make_float2(w1.x * w2.x - w1.y * w2.y, w1.x * w2.y + w1.y * w2.x);

        const float2 t1 = make_float2(x1.x * w1.x - x1.y * w1.y, x1.x * w1.y + x1.y * w1.x);
        const float2 t2 = make_float2(x2.x * w2.x - x2.y * w2.y, x2.x * w2.y + x2.y * w2.x);
        const float2 t3 = make_float2(x3.x * w3.x - x3.y * w3.y, x3.x * w3.y + x3.y * w3.x);

        const float ax = t0.x + t2.x;
        const float bx = t0.x - t2.x;
        const float cx = t1.x + t3.x;
        const float dx = -(t1.y - t3.y);

        o[k]        = (ax + cx) * scale;
        o[k + 1024] = (bx + dx) * scale;
        o[k + 2048] = (ax - cx) * scale;
        o[k + 3072] = (bx - dx) * scale;
    }
}

extern "C" void kernel_launch(void* const* d_in, const int* in_sizes, int n_in,
                              void* d_out, int out_size) {
    const float* w_re   = (const float*)d_in[0];
    const float* w_im   = (const float*)d_in[1];
    const float* p_re   = (const float*)d_in[2];
    const float* p_im   = (const float*)d_in[3];
    const float* B_re   = (const float*)d_in[4];
    const float* B_im   = (const float*)d_in[5];
    const float* C_re   = (const float*)d_in[6];
    const float* C_im   = (const float*)d_in[7];
    const float* log_dt = (const float*)d_in[8];
    float* out = (float*)d_out;

    dim3 g1(4, HDIM);
    cauchy_kernel<<<g1, 256>>>(w_re, w_im, p_re, p_im, B_re, B_im, C_re, C_im, log_dt);
    ifft_kernel<<<HDIM, 512>>>(out);
}